// round 16
// baseline (speedup 1.0000x reference)
#include <cuda_runtime.h>
#include <cuda_fp16.h>
#include <cstdint>

#define D 64
#define NMAX 100000
#define EMAX 1600000
#define SCALE 0.125f  // D^-0.5 = 1/8

// Scratch (device globals: allocation-free per harness rules)
__device__ __half g_Qh[NMAX * D];
__device__ __half g_Kh[NMAX * D];
__device__ __half g_Vh[NMAX * D];
__device__ int g_cnt[NMAX];
__device__ int g_offs[NMAX];
__device__ int g_cursor[NMAX];
__device__ int g_ssend[EMAX];
__device__ int g_total;

__device__ __forceinline__ uint32_t smem_u32(const void* p) {
    uint32_t a;
    asm("{ .reg .u64 t; cvta.to.shared.u64 t, %1; cvt.u32.u64 %0, t; }"
        : "=r"(a) : "l"(p));
    return a;
}
__device__ __forceinline__ void ldsm_x4(uint32_t& r0, uint32_t& r1,
                                        uint32_t& r2, uint32_t& r3,
                                        uint32_t addr) {
    asm volatile("ldmatrix.sync.aligned.m8n8.x4.shared.b16 {%0,%1,%2,%3}, [%4];"
                 : "=r"(r0), "=r"(r1), "=r"(r2), "=r"(r3) : "r"(addr));
}
__device__ __forceinline__ void ldsm_x2(uint32_t& r0, uint32_t& r1,
                                        uint32_t addr) {
    asm volatile("ldmatrix.sync.aligned.m8n8.x2.shared.b16 {%0,%1}, [%2];"
                 : "=r"(r0), "=r"(r1) : "r"(addr));
}
__device__ __forceinline__ void mma_16816(float* c, uint32_t a0, uint32_t a1,
                                          uint32_t a2, uint32_t a3,
                                          uint32_t b0, uint32_t b1) {
    asm volatile(
        "mma.sync.aligned.m16n8k16.row.col.f32.f16.f16.f32 "
        "{%0,%1,%2,%3}, {%4,%5,%6,%7}, {%8,%9}, {%0,%1,%2,%3};"
        : "+f"(c[0]), "+f"(c[1]), "+f"(c[2]), "+f"(c[3])
        : "r"(a0), "r"(a1), "r"(a2), "r"(a3), "r"(b0), "r"(b1));
}

#define PA 72  // smem pitch in halves: 144B row stride, conflict-free ldmatrix

// ---------------------------------------------------------------------------
// CSR construction, scan-free (segments need not be receiver-ordered).
// NOTE (R8-R10 lesson): replay-state resets live ONLY in zero_cnt_kernel.
// ---------------------------------------------------------------------------
__global__ void zero_cnt_kernel(int N) {
    int i = blockIdx.x * blockDim.x + threadIdx.x;
    if (i < N) g_cnt[i] = 0;
    if (i == 0) g_total = 0;
}

__global__ void hist_kernel(const int* __restrict__ ei, int E) {
    int i = blockIdx.x * blockDim.x + threadIdx.x;
    if (i < E) atomicAdd(&g_cnt[__ldg(&ei[E + i])], 1);
}

__global__ void assign_kernel(int N) {
    int i = blockIdx.x * blockDim.x + threadIdx.x;
    if (i < N) {
        int c = g_cnt[i];
        int base = atomicAdd(&g_total, c);
        g_offs[i] = base;
        g_cursor[i] = base;
    }
}

__global__ void scatter_kernel(const int* __restrict__ ei, int E) {
    int i = blockIdx.x * blockDim.x + threadIdx.x;
    if (i < E) {
        int snd = __ldg(&ei[i]);
        int rcv = __ldg(&ei[E + i]);
        int pos = atomicAdd(&g_cursor[rcv], 1);
        g_ssend[pos] = snd;
    }
}

// ---------------------------------------------------------------------------
// Fused QKV projection via HMMA (fp32 accum, fp16 stores). 128-row tile,
// 256 threads, 3 passes over one smem W buffer. (Hidden under CSR branch.)
// ---------------------------------------------------------------------------
__global__ void __launch_bounds__(256) qkv_kernel(
    const float* __restrict__ x,
    const float* __restrict__ Wq,
    const float* __restrict__ Wk,
    const float* __restrict__ Wv, int N) {
    __shared__ __half sA[128 * PA];
    __shared__ __half sW[64 * PA];  // W^T: sW[n][k]

    const int tid = threadIdx.x;
    const int lane = tid & 31;
    const int warp = tid >> 5;
    const int tile0 = blockIdx.x * 128;

    for (int i = tid; i < 128 * 16; i += 256) {
        int row = i >> 4;
        int c4 = i & 15;
        int grow = tile0 + row;
        float4 v = make_float4(0.f, 0.f, 0.f, 0.f);
        if (grow < N) v = reinterpret_cast<const float4*>(x + (size_t)grow * D)[c4];
        __half2 h0 = __floats2half2_rn(v.x, v.y);
        __half2 h1 = __floats2half2_rn(v.z, v.w);
        uint2 pkt = make_uint2(*reinterpret_cast<uint32_t*>(&h0),
                               *reinterpret_cast<uint32_t*>(&h1));
        *reinterpret_cast<uint2*>(&sA[row * PA + c4 * 4]) = pkt;
    }

    const uint32_t sA_u = smem_u32(sA);
    const uint32_t sW_u = smem_u32(sW);

    const int mrow = warp * 16 + (lane & 7) + ((lane >> 3) & 1) * 8;
    const int acol = (lane >> 4) * 8;
    const uint32_t aBase = sA_u + (mrow * PA + acol) * 2;
    const int l15 = lane & 15;
    const int nrow_l = l15 & 7;
    const int bcol = ((l15 >> 3) & 1) * 8;

    const int gid = lane >> 2;
    const int tig = lane & 3;

    const float* Ws[3] = {Wq, Wk, Wv};
    __half* Gs[3] = {g_Qh, g_Kh, g_Vh};

#pragma unroll
    for (int p = 0; p < 3; p++) {
        __syncthreads();
        for (int i = tid; i < 64 * 16; i += 256) {
            int k = i >> 4;
            int c4 = i & 15;
            float4 w = __ldg(reinterpret_cast<const float4*>(Ws[p] + k * D + c4 * 4));
            sW[(c4 * 4 + 0) * PA + k] = __float2half_rn(w.x);
            sW[(c4 * 4 + 1) * PA + k] = __float2half_rn(w.y);
            sW[(c4 * 4 + 2) * PA + k] = __float2half_rn(w.z);
            sW[(c4 * 4 + 3) * PA + k] = __float2half_rn(w.w);
        }
        __syncthreads();

        float acc[8][4];
#pragma unroll
        for (int nt = 0; nt < 8; nt++)
#pragma unroll
            for (int q = 0; q < 4; q++) acc[nt][q] = 0.f;

#pragma unroll
        for (int k = 0; k < 4; k++) {
            uint32_t a0, a1, a2, a3;
            ldsm_x4(a0, a1, a2, a3, aBase + k * 32);
#pragma unroll
            for (int nt = 0; nt < 8; nt++) {
                uint32_t b0, b1;
                ldsm_x2(b0, b1,
                        sW_u + ((nt * 8 + nrow_l) * PA + k * 16 + bcol) * 2);
                mma_16816(acc[nt], a0, a1, a2, a3, b0, b1);
            }
        }

        __half* G = Gs[p];
        int r_lo = tile0 + warp * 16 + gid;
        int r_hi = r_lo + 8;
#pragma unroll
        for (int nt = 0; nt < 8; nt++) {
            int col = nt * 8 + tig * 2;
            if (r_lo < N)
                *reinterpret_cast<__half2*>(G + (size_t)r_lo * D + col) =
                    __floats2half2_rn(acc[nt][0], acc[nt][1]);
            if (r_hi < N)
                *reinterpret_cast<__half2*>(G + (size_t)r_hi * D + col) =
                    __floats2half2_rn(acc[nt][2], acc[nt][3]);
        }
    }
}

// ---------------------------------------------------------------------------
// Fused aggregation + output projection. 512 threads = 16 warps = 16
// consecutive receivers per block. Each warp aggregates its receiver
// (octet-parallel, fp32 registers, no atomics), writes h into a 16x64 fp16
// smem tile; then warps 0-7 run one m16n8k16 HMMA tile against smem Wo^T and
// write out = x + h@Wo. No g_Hh round-trip, no separate out kernel.
// ---------------------------------------------------------------------------
__global__ void __launch_bounds__(512) aggregate_out_kernel(
    const float* __restrict__ x,
    const float* __restrict__ Wo,
    float* __restrict__ out, int N) {
    __shared__ __half sH[16 * PA];
    __shared__ __half sW[64 * PA];  // Wo^T: sW[n][k]

    const int tid = threadIdx.x;
    const int lane = tid & 31;
    const int warp = tid >> 5;       // 0..15
    const int tile0 = blockIdx.x * 16;
    const int rcv = tile0 + warp;
    const int oct = lane >> 3;
    const int ol = lane & 7;

    // Stage Wo^T first — overlaps with the aggregation loop below.
    for (int i = tid; i < 64 * 16; i += 512) {
        int k = i >> 4;
        int c4 = i & 15;
        float4 w = __ldg(reinterpret_cast<const float4*>(Wo + k * D + c4 * 4));
        sW[(c4 * 4 + 0) * PA + k] = __float2half_rn(w.x);
        sW[(c4 * 4 + 1) * PA + k] = __float2half_rn(w.y);
        sW[(c4 * 4 + 2) * PA + k] = __float2half_rn(w.z);
        sW[(c4 * 4 + 3) * PA + k] = __float2half_rn(w.w);
    }

    // ---- aggregation (per-warp, unchanged math) ----
    float acc[8];
#pragma unroll
    for (int i = 0; i < 8; i++) acc[i] = 0.f;
    float denom = 0.f;

    if (rcv < N) {
        int start = g_offs[rcv];
        int cnt = g_cnt[rcv];
        int end = start + cnt;

        uint4 qu = reinterpret_cast<const uint4*>(g_Qh + (size_t)rcv * D)[ol];
        float2 q0 = __half22float2(*reinterpret_cast<__half2*>(&qu.x));
        float2 q1 = __half22float2(*reinterpret_cast<__half2*>(&qu.y));
        float2 q2 = __half22float2(*reinterpret_cast<__half2*>(&qu.z));
        float2 q3 = __half22float2(*reinterpret_cast<__half2*>(&qu.w));

        int iters = (cnt + 3) >> 2;
        for (int it = 0; it < iters; it++) {
            int eb = start + it * 4 + oct;
            bool ok = eb < end;
            int snd = ok ? g_ssend[eb] : 0;

            uint4 ku = reinterpret_cast<const uint4*>(g_Kh + (size_t)snd * D)[ol];
            float2 k0 = __half22float2(*reinterpret_cast<__half2*>(&ku.x));
            float2 k1 = __half22float2(*reinterpret_cast<__half2*>(&ku.y));
            float2 k2 = __half22float2(*reinterpret_cast<__half2*>(&ku.z));
            float2 k3 = __half22float2(*reinterpret_cast<__half2*>(&ku.w));

            float part = q0.x * k0.x + q0.y * k0.y + q1.x * k1.x + q1.y * k1.y
                       + q2.x * k2.x + q2.y * k2.y + q3.x * k3.x + q3.y * k3.y;
            part += __shfl_xor_sync(0xffffffffu, part, 1);
            part += __shfl_xor_sync(0xffffffffu, part, 2);
            part += __shfl_xor_sync(0xffffffffu, part, 4);

            float p = ok ? __expf(part * SCALE) : 0.f;

            uint4 vu = reinterpret_cast<const uint4*>(g_Vh + (size_t)snd * D)[ol];
            float2 v0 = __half22float2(*reinterpret_cast<__half2*>(&vu.x));
            float2 v1 = __half22float2(*reinterpret_cast<__half2*>(&vu.y));
            float2 v2 = __half22float2(*reinterpret_cast<__half2*>(&vu.z));
            float2 v3 = __half22float2(*reinterpret_cast<__half2*>(&vu.w));

            acc[0] = fmaf(p, v0.x, acc[0]); acc[1] = fmaf(p, v0.y, acc[1]);
            acc[2] = fmaf(p, v1.x, acc[2]); acc[3] = fmaf(p, v1.y, acc[3]);
            acc[4] = fmaf(p, v2.x, acc[4]); acc[5] = fmaf(p, v2.y, acc[5]);
            acc[6] = fmaf(p, v3.x, acc[6]); acc[7] = fmaf(p, v3.y, acc[7]);
            denom += p;
        }
    }

#pragma unroll
    for (int i = 0; i < 8; i++) {
        acc[i] += __shfl_xor_sync(0xffffffffu, acc[i], 8);
        acc[i] += __shfl_xor_sync(0xffffffffu, acc[i], 16);
    }
    denom += __shfl_xor_sync(0xffffffffu, denom, 8);
    denom += __shfl_xor_sync(0xffffffffu, denom, 16);

    // h row -> smem tile (zeros for out-of-range receivers keep GEMM defined)
    if (oct == 0) {
        uint4 pkt = make_uint4(0u, 0u, 0u, 0u);
        if (rcv < N) {
            float inv = denom > 0.f ? 1.0f / denom : 0.f;
            __half2 h0 = __floats2half2_rn(acc[0] * inv, acc[1] * inv);
            __half2 h1 = __floats2half2_rn(acc[2] * inv, acc[3] * inv);
            __half2 h2 = __floats2half2_rn(acc[4] * inv, acc[5] * inv);
            __half2 h3 = __floats2half2_rn(acc[6] * inv, acc[7] * inv);
            pkt = make_uint4(*reinterpret_cast<uint32_t*>(&h0),
                             *reinterpret_cast<uint32_t*>(&h1),
                             *reinterpret_cast<uint32_t*>(&h2),
                             *reinterpret_cast<uint32_t*>(&h3));
        }
        *reinterpret_cast<uint4*>(&sH[warp * PA + ol * 8]) = pkt;
    }
    __syncthreads();

    // ---- output GEMM: warps 0-7 each own one 8-col n-tile of the m16 tile ----
    if (warp < 8) {
        const uint32_t sH_u = smem_u32(sH);
        const uint32_t sW_u = smem_u32(sW);

        const int mrow = (lane & 7) + ((lane >> 3) & 1) * 8;
        const int acol = (lane >> 4) * 8;
        const uint32_t aBase = sH_u + (mrow * PA + acol) * 2;
        const int l15 = lane & 15;
        const int nrow_l = l15 & 7;
        const int bcol = ((l15 >> 3) & 1) * 8;

        float oacc[4] = {0.f, 0.f, 0.f, 0.f};
#pragma unroll
        for (int k = 0; k < 4; k++) {
            uint32_t a0, a1, a2, a3;
            ldsm_x4(a0, a1, a2, a3, aBase + k * 32);
            uint32_t b0, b1;
            ldsm_x2(b0, b1,
                    sW_u + ((warp * 8 + nrow_l) * PA + k * 16 + bcol) * 2);
            mma_16816(oacc, a0, a1, a2, a3, b0, b1);
        }

        const int gid = lane >> 2;
        const int tig = lane & 3;
        int r_lo = tile0 + gid;
        int r_hi = r_lo + 8;
        int col = warp * 8 + tig * 2;
        if (r_lo < N) {
            float2 xr = *reinterpret_cast<const float2*>(x + (size_t)r_lo * D + col);
            *reinterpret_cast<float2*>(out + (size_t)r_lo * D + col) =
                make_float2(xr.x + oacc[0], xr.y + oacc[1]);
        }
        if (r_hi < N) {
            float2 xr = *reinterpret_cast<const float2*>(x + (size_t)r_hi * D + col);
            *reinterpret_cast<float2*>(out + (size_t)r_hi * D + col) =
                make_float2(xr.x + oacc[2], xr.y + oacc[3]);
        }
    }
}

// ---------------------------------------------------------------------------
// Launch: fork the CSR chain onto a side stream so it overlaps qkv.
// ---------------------------------------------------------------------------
extern "C" void kernel_launch(void* const* d_in, const int* in_sizes, int n_in,
                              void* d_out, int out_size) {
    const float* x  = (const float*)d_in[0];
    const int*   ei = (const int*)d_in[1];
    const float* Wq = (const float*)d_in[2];
    const float* Wk = (const float*)d_in[3];
    const float* Wv = (const float*)d_in[4];
    const float* Wo = (const float*)d_in[5];
    float* out = (float*)d_out;

    int N = in_sizes[0] / D;
    int E = in_sizes[1] / 2;

    int tiles = (N + 127) / 128;
    int aggblocks = (N + 15) / 16;

    static cudaStream_t s1 = nullptr;
    static cudaEvent_t ev_fork = nullptr;
    static cudaEvent_t ev_join = nullptr;
    if (s1 == nullptr) {
        cudaStreamCreateWithFlags(&s1, cudaStreamNonBlocking);
        cudaEventCreateWithFlags(&ev_fork, cudaEventDisableTiming);
        cudaEventCreateWithFlags(&ev_join, cudaEventDisableTiming);
    }

    // Fork: CSR chain on s1, projections on the origin (legacy) stream.
    cudaEventRecord(ev_fork, (cudaStream_t)0);
    cudaStreamWaitEvent(s1, ev_fork, 0);

    zero_cnt_kernel<<<(N + 255) / 256, 256, 0, s1>>>(N);
    hist_kernel<<<(E + 255) / 256, 256, 0, s1>>>(ei, E);
    assign_kernel<<<(N + 255) / 256, 256, 0, s1>>>(N);
    scatter_kernel<<<(E + 255) / 256, 256, 0, s1>>>(ei, E);
    cudaEventRecord(ev_join, s1);

    qkv_kernel<<<tiles, 256>>>(x, Wq, Wk, Wv, N);

    // Join: fused aggregate+out needs both CSR (s1) and Q/K/V (origin).
    cudaStreamWaitEvent((cudaStream_t)0, ev_join, 0);
    aggregate_out_kernel<<<aggblocks, 512>>>(x, Wo, out, N);
}

// round 17
// speedup vs baseline: 1.2601x; 1.2601x over previous
#include <cuda_runtime.h>
#include <cuda_fp16.h>
#include <cstdint>

#define D 64
#define NMAX 100000
#define EMAX 1600000
#define SCALE 0.125f  // D^-0.5 = 1/8

// Scratch (device globals: allocation-free per harness rules)
__device__ __half g_Qh[NMAX * D];
__device__ __half g_Kh[NMAX * D];
__device__ __half g_Vh[NMAX * D];
__device__ __half g_Hh[NMAX * D];     // h = softmax-aggregated V (normalized)
__device__ int g_cnt[NMAX];
__device__ int g_offs[NMAX];
__device__ int g_cursor[NMAX];
__device__ int g_ssend[EMAX];
__device__ int g_total;

__device__ __forceinline__ uint32_t smem_u32(const void* p) {
    uint32_t a;
    asm("{ .reg .u64 t; cvta.to.shared.u64 t, %1; cvt.u32.u64 %0, t; }"
        : "=r"(a) : "l"(p));
    return a;
}
__device__ __forceinline__ void ldsm_x4(uint32_t& r0, uint32_t& r1,
                                        uint32_t& r2, uint32_t& r3,
                                        uint32_t addr) {
    asm volatile("ldmatrix.sync.aligned.m8n8.x4.shared.b16 {%0,%1,%2,%3}, [%4];"
                 : "=r"(r0), "=r"(r1), "=r"(r2), "=r"(r3) : "r"(addr));
}
__device__ __forceinline__ void ldsm_x2(uint32_t& r0, uint32_t& r1,
                                        uint32_t addr) {
    asm volatile("ldmatrix.sync.aligned.m8n8.x2.shared.b16 {%0,%1}, [%2];"
                 : "=r"(r0), "=r"(r1) : "r"(addr));
}
__device__ __forceinline__ void mma_16816(float* c, uint32_t a0, uint32_t a1,
                                          uint32_t a2, uint32_t a3,
                                          uint32_t b0, uint32_t b1) {
    asm volatile(
        "mma.sync.aligned.m16n8k16.row.col.f32.f16.f16.f32 "
        "{%0,%1,%2,%3}, {%4,%5,%6,%7}, {%8,%9}, {%0,%1,%2,%3};"
        : "+f"(c[0]), "+f"(c[1]), "+f"(c[2]), "+f"(c[3])
        : "r"(a0), "r"(a1), "r"(a2), "r"(a3), "r"(b0), "r"(b1));
}

#define PA 72  // smem pitch in halves: 144B row stride, conflict-free ldmatrix

// ---------------------------------------------------------------------------
// CSR construction, scan-free (segments need not be receiver-ordered).
// NOTE (R8-R10 lesson): replay-state resets live ONLY in zero_cnt_kernel.
// ---------------------------------------------------------------------------
__global__ void zero_cnt_kernel(int N) {
    int i = blockIdx.x * blockDim.x + threadIdx.x;
    if (i < N) g_cnt[i] = 0;
    if (i == 0) g_total = 0;
}

__global__ void hist_kernel(const int* __restrict__ ei, int E) {
    int i = blockIdx.x * blockDim.x + threadIdx.x;
    if (i < E) atomicAdd(&g_cnt[__ldg(&ei[E + i])], 1);
}

__global__ void assign_kernel(int N) {
    int i = blockIdx.x * blockDim.x + threadIdx.x;
    if (i < N) {
        int c = g_cnt[i];
        int base = atomicAdd(&g_total, c);
        g_offs[i] = base;
        g_cursor[i] = base;
    }
}

__global__ void scatter_kernel(const int* __restrict__ ei, int E) {
    int i = blockIdx.x * blockDim.x + threadIdx.x;
    if (i < E) {
        int snd = __ldg(&ei[i]);
        int rcv = __ldg(&ei[E + i]);
        int pos = atomicAdd(&g_cursor[rcv], 1);
        g_ssend[pos] = snd;
    }
}

// ---------------------------------------------------------------------------
// Fused QKV projection via HMMA (fp32 accum, fp16 stores). 128-row tile,
// 256 threads, 3 passes over one smem W buffer. (Hidden under CSR branch.)
// ---------------------------------------------------------------------------
__global__ void __launch_bounds__(256) qkv_kernel(
    const float* __restrict__ x,
    const float* __restrict__ Wq,
    const float* __restrict__ Wk,
    const float* __restrict__ Wv, int N) {
    __shared__ __half sA[128 * PA];
    __shared__ __half sW[64 * PA];  // W^T: sW[n][k]

    const int tid = threadIdx.x;
    const int lane = tid & 31;
    const int warp = tid >> 5;
    const int tile0 = blockIdx.x * 128;

    for (int i = tid; i < 128 * 16; i += 256) {
        int row = i >> 4;
        int c4 = i & 15;
        int grow = tile0 + row;
        float4 v = make_float4(0.f, 0.f, 0.f, 0.f);
        if (grow < N) v = reinterpret_cast<const float4*>(x + (size_t)grow * D)[c4];
        __half2 h0 = __floats2half2_rn(v.x, v.y);
        __half2 h1 = __floats2half2_rn(v.z, v.w);
        uint2 pkt = make_uint2(*reinterpret_cast<uint32_t*>(&h0),
                               *reinterpret_cast<uint32_t*>(&h1));
        *reinterpret_cast<uint2*>(&sA[row * PA + c4 * 4]) = pkt;
    }

    const uint32_t sA_u = smem_u32(sA);
    const uint32_t sW_u = smem_u32(sW);

    const int mrow = warp * 16 + (lane & 7) + ((lane >> 3) & 1) * 8;
    const int acol = (lane >> 4) * 8;
    const uint32_t aBase = sA_u + (mrow * PA + acol) * 2;
    const int l15 = lane & 15;
    const int nrow_l = l15 & 7;
    const int bcol = ((l15 >> 3) & 1) * 8;

    const int gid = lane >> 2;
    const int tig = lane & 3;

    const float* Ws[3] = {Wq, Wk, Wv};
    __half* Gs[3] = {g_Qh, g_Kh, g_Vh};

#pragma unroll
    for (int p = 0; p < 3; p++) {
        __syncthreads();
        for (int i = tid; i < 64 * 16; i += 256) {
            int k = i >> 4;
            int c4 = i & 15;
            float4 w = __ldg(reinterpret_cast<const float4*>(Ws[p] + k * D + c4 * 4));
            sW[(c4 * 4 + 0) * PA + k] = __float2half_rn(w.x);
            sW[(c4 * 4 + 1) * PA + k] = __float2half_rn(w.y);
            sW[(c4 * 4 + 2) * PA + k] = __float2half_rn(w.z);
            sW[(c4 * 4 + 3) * PA + k] = __float2half_rn(w.w);
        }
        __syncthreads();

        float acc[8][4];
#pragma unroll
        for (int nt = 0; nt < 8; nt++)
#pragma unroll
            for (int q = 0; q < 4; q++) acc[nt][q] = 0.f;

#pragma unroll
        for (int k = 0; k < 4; k++) {
            uint32_t a0, a1, a2, a3;
            ldsm_x4(a0, a1, a2, a3, aBase + k * 32);
#pragma unroll
            for (int nt = 0; nt < 8; nt++) {
                uint32_t b0, b1;
                ldsm_x2(b0, b1,
                        sW_u + ((nt * 8 + nrow_l) * PA + k * 16 + bcol) * 2);
                mma_16816(acc[nt], a0, a1, a2, a3, b0, b1);
            }
        }

        __half* G = Gs[p];
        int r_lo = tile0 + warp * 16 + gid;
        int r_hi = r_lo + 8;
#pragma unroll
        for (int nt = 0; nt < 8; nt++) {
            int col = nt * 8 + tig * 2;
            if (r_lo < N)
                *reinterpret_cast<__half2*>(G + (size_t)r_lo * D + col) =
                    __floats2half2_rn(acc[nt][0], acc[nt][1]);
            if (r_hi < N)
                *reinterpret_cast<__half2*>(G + (size_t)r_hi * D + col) =
                    __floats2half2_rn(acc[nt][2], acc[nt][3]);
        }
    }
}

// ---------------------------------------------------------------------------
// CSR aggregation, octet-parallel, sender-batched: one warp per receiver,
// 4 edges in flight; sender indices for 32 edges loaded in ONE coalesced
// load per lane and distributed via shfl, removing the dependent sender
// load (~240cyc L2) from every iteration's K/V gather chain.
// fp32 register accumulation, no atomics.
// ---------------------------------------------------------------------------
__global__ void __launch_bounds__(256) aggregate_kernel(int N) {
    int wg = (blockIdx.x * blockDim.x + threadIdx.x) >> 5;
    int lane = threadIdx.x & 31;
    if (wg >= N) return;
    int rcv = wg;
    int oct = lane >> 3;   // 0..3 : which edge of the quad
    int ol = lane & 7;     // 0..7 : 8 halves of the row

    int start = g_offs[rcv];
    int cnt = g_cnt[rcv];
    int end = start + cnt;

    uint4 qu = reinterpret_cast<const uint4*>(g_Qh + (size_t)rcv * D)[ol];
    float2 q0 = __half22float2(*reinterpret_cast<__half2*>(&qu.x));
    float2 q1 = __half22float2(*reinterpret_cast<__half2*>(&qu.y));
    float2 q2 = __half22float2(*reinterpret_cast<__half2*>(&qu.z));
    float2 q3 = __half22float2(*reinterpret_cast<__half2*>(&qu.w));

    float acc[8];
#pragma unroll
    for (int i = 0; i < 8; i++) acc[i] = 0.f;
    float denom = 0.f;

    for (int base = start; base < end; base += 32) {
        // One coalesced sender batch for up to 32 edges.
        int sreg = (base + lane < end) ? g_ssend[base + lane] : 0;
        int nq = min(8, (end - base + 3) >> 2);  // quad-iterations this batch

        for (int j = 0; j < nq; j++) {
            int eoff = j * 4 + oct;
            bool ok = base + eoff < end;
            int snd = __shfl_sync(0xffffffffu, sreg, eoff);

            uint4 ku = reinterpret_cast<const uint4*>(g_Kh + (size_t)snd * D)[ol];
            float2 k0 = __half22float2(*reinterpret_cast<__half2*>(&ku.x));
            float2 k1 = __half22float2(*reinterpret_cast<__half2*>(&ku.y));
            float2 k2 = __half22float2(*reinterpret_cast<__half2*>(&ku.z));
            float2 k3 = __half22float2(*reinterpret_cast<__half2*>(&ku.w));

            float part = q0.x * k0.x + q0.y * k0.y + q1.x * k1.x + q1.y * k1.y
                       + q2.x * k2.x + q2.y * k2.y + q3.x * k3.x + q3.y * k3.y;
            part += __shfl_xor_sync(0xffffffffu, part, 1);
            part += __shfl_xor_sync(0xffffffffu, part, 2);
            part += __shfl_xor_sync(0xffffffffu, part, 4);

            float p = ok ? __expf(part * SCALE) : 0.f;

            uint4 vu = reinterpret_cast<const uint4*>(g_Vh + (size_t)snd * D)[ol];
            float2 v0 = __half22float2(*reinterpret_cast<__half2*>(&vu.x));
            float2 v1 = __half22float2(*reinterpret_cast<__half2*>(&vu.y));
            float2 v2 = __half22float2(*reinterpret_cast<__half2*>(&vu.z));
            float2 v3 = __half22float2(*reinterpret_cast<__half2*>(&vu.w));

            acc[0] = fmaf(p, v0.x, acc[0]); acc[1] = fmaf(p, v0.y, acc[1]);
            acc[2] = fmaf(p, v1.x, acc[2]); acc[3] = fmaf(p, v1.y, acc[3]);
            acc[4] = fmaf(p, v2.x, acc[4]); acc[5] = fmaf(p, v2.y, acc[5]);
            acc[6] = fmaf(p, v3.x, acc[6]); acc[7] = fmaf(p, v3.y, acc[7]);
            denom += p;
        }
    }

#pragma unroll
    for (int i = 0; i < 8; i++) {
        acc[i] += __shfl_xor_sync(0xffffffffu, acc[i], 8);
        acc[i] += __shfl_xor_sync(0xffffffffu, acc[i], 16);
    }
    denom += __shfl_xor_sync(0xffffffffu, denom, 8);
    denom += __shfl_xor_sync(0xffffffffu, denom, 16);

    if (oct == 0) {
        float inv = denom > 0.f ? 1.0f / denom : 0.f;
        __half2 h0 = __floats2half2_rn(acc[0] * inv, acc[1] * inv);
        __half2 h1 = __floats2half2_rn(acc[2] * inv, acc[3] * inv);
        __half2 h2 = __floats2half2_rn(acc[4] * inv, acc[5] * inv);
        __half2 h3 = __floats2half2_rn(acc[6] * inv, acc[7] * inv);
        uint4 pkt = make_uint4(*reinterpret_cast<uint32_t*>(&h0),
                               *reinterpret_cast<uint32_t*>(&h1),
                               *reinterpret_cast<uint32_t*>(&h2),
                               *reinterpret_cast<uint32_t*>(&h3));
        reinterpret_cast<uint4*>(g_Hh + (size_t)rcv * D)[ol] = pkt;
    }
}

// ---------------------------------------------------------------------------
// Output: out = x + h @ Wo via HMMA. 128-row tile, 256 threads. (R14 form.)
// ---------------------------------------------------------------------------
__global__ void __launch_bounds__(256) out_kernel(
    const float* __restrict__ x,
    const float* __restrict__ Wo,
    float* __restrict__ out, int N) {
    __shared__ __half sA[128 * PA];
    __shared__ __half sW[64 * PA];

    const int tid = threadIdx.x;
    const int lane = tid & 31;
    const int warp = tid >> 5;
    const int tile0 = blockIdx.x * 128;

    for (int i = tid; i < 128 * 8; i += 256) {
        int row = i >> 3;
        int c8 = i & 7;
        int grow = tile0 + row;
        uint4 pkt = make_uint4(0u, 0u, 0u, 0u);
        if (grow < N)
            pkt = reinterpret_cast<const uint4*>(g_Hh + (size_t)grow * D)[c8];
        *reinterpret_cast<uint4*>(&sA[row * PA + c8 * 8]) = pkt;
    }
    for (int i = tid; i < 64 * 16; i += 256) {
        int k = i >> 4;
        int c4 = i & 15;
        float4 w = __ldg(reinterpret_cast<const float4*>(Wo + k * D + c4 * 4));
        sW[(c4 * 4 + 0) * PA + k] = __float2half_rn(w.x);
        sW[(c4 * 4 + 1) * PA + k] = __float2half_rn(w.y);
        sW[(c4 * 4 + 2) * PA + k] = __float2half_rn(w.z);
        sW[(c4 * 4 + 3) * PA + k] = __float2half_rn(w.w);
    }
    __syncthreads();

    const uint32_t sA_u = smem_u32(sA);
    const uint32_t sW_u = smem_u32(sW);

    const int mrow = warp * 16 + (lane & 7) + ((lane >> 3) & 1) * 8;
    const int acol = (lane >> 4) * 8;
    const uint32_t aBase = sA_u + (mrow * PA + acol) * 2;
    const int l15 = lane & 15;
    const int nrow_l = l15 & 7;
    const int bcol = ((l15 >> 3) & 1) * 8;

    float acc[8][4];
#pragma unroll
    for (int nt = 0; nt < 8; nt++)
#pragma unroll
        for (int q = 0; q < 4; q++) acc[nt][q] = 0.f;

#pragma unroll
    for (int k = 0; k < 4; k++) {
        uint32_t a0, a1, a2, a3;
        ldsm_x4(a0, a1, a2, a3, aBase + k * 32);
#pragma unroll
        for (int nt = 0; nt < 8; nt++) {
            uint32_t b0, b1;
            ldsm_x2(b0, b1, sW_u + ((nt * 8 + nrow_l) * PA + k * 16 + bcol) * 2);
            mma_16816(acc[nt], a0, a1, a2, a3, b0, b1);
        }
    }

    const int gid = lane >> 2;
    const int tig = lane & 3;
    int r_lo = tile0 + warp * 16 + gid;
    int r_hi = r_lo + 8;
#pragma unroll
    for (int nt = 0; nt < 8; nt++) {
        int col = nt * 8 + tig * 2;
        if (r_lo < N) {
            float2 xr = *reinterpret_cast<const float2*>(x + (size_t)r_lo * D + col);
            *reinterpret_cast<float2*>(out + (size_t)r_lo * D + col) =
                make_float2(xr.x + acc[nt][0], xr.y + acc[nt][1]);
        }
        if (r_hi < N) {
            float2 xr = *reinterpret_cast<const float2*>(x + (size_t)r_hi * D + col);
            *reinterpret_cast<float2*>(out + (size_t)r_hi * D + col) =
                make_float2(xr.x + acc[nt][2], xr.y + acc[nt][3]);
        }
    }
}

// ---------------------------------------------------------------------------
// Launch: fork the CSR chain onto a side stream so it overlaps qkv.
// ---------------------------------------------------------------------------
extern "C" void kernel_launch(void* const* d_in, const int* in_sizes, int n_in,
                              void* d_out, int out_size) {
    const float* x  = (const float*)d_in[0];
    const int*   ei = (const int*)d_in[1];
    const float* Wq = (const float*)d_in[2];
    const float* Wk = (const float*)d_in[3];
    const float* Wv = (const float*)d_in[4];
    const float* Wo = (const float*)d_in[5];
    float* out = (float*)d_out;

    int N = in_sizes[0] / D;
    int E = in_sizes[1] / 2;

    int tiles = (N + 127) / 128;

    static cudaStream_t s1 = nullptr;
    static cudaEvent_t ev_fork = nullptr;
    static cudaEvent_t ev_join = nullptr;
    if (s1 == nullptr) {
        cudaStreamCreateWithFlags(&s1, cudaStreamNonBlocking);
        cudaEventCreateWithFlags(&ev_fork, cudaEventDisableTiming);
        cudaEventCreateWithFlags(&ev_join, cudaEventDisableTiming);
    }

    // Fork: CSR chain on s1, projections on the origin (legacy) stream.
    cudaEventRecord(ev_fork, (cudaStream_t)0);
    cudaStreamWaitEvent(s1, ev_fork, 0);

    zero_cnt_kernel<<<(N + 255) / 256, 256, 0, s1>>>(N);
    hist_kernel<<<(E + 255) / 256, 256, 0, s1>>>(ei, E);
    assign_kernel<<<(N + 255) / 256, 256, 0, s1>>>(N);
    scatter_kernel<<<(E + 255) / 256, 256, 0, s1>>>(ei, E);
    cudaEventRecord(ev_join, s1);

    qkv_kernel<<<tiles, 256>>>(x, Wq, Wk, Wv, N);

    // Join: aggregate needs both CSR (s1) and Q/K/V (origin).
    cudaStreamWaitEvent((cudaStream_t)0, ev_join, 0);
    aggregate_kernel<<<(N * 32 + 255) / 256, 256>>>(N);
    out_kernel<<<tiles, 256>>>(x, Wo, out, N);
}